// round 16
// baseline (speedup 1.0000x reference)
#include <cuda_runtime.h>
#include <cuda_fp16.h>
#include <cstdint>
#include <math.h>

#define DIM   128
#define HID   384
#define BB    4
#define ND    100000
#define NTOK  400000
#define NL    4096
#define EE    200000
#define EPS   1e-5f

// ---------------- scratch (device globals; no allocations allowed) ----------
// NOTE: reference these symbols ONLY from device code (Round-5 ATS lesson).
__device__ float  g_vact[(size_t)NTOK * DIM];       // 204.8 MB
__device__ float  g_l[(size_t)BB * NL * DIM];       // 8.4 MB
// Weights stored as pre-swizzled 16KB smem-image blocks, one per (c, n0half):
// img index = c*2 + n0half, 6 images of 8192 halfs per set.
__device__ __half g_w1h[2][6 * 8192];
__device__ __half g_w3h[2][6 * 8192];
__device__ __half g_w2h[2][6 * 8192];
__device__ int    g_hist[NL];
__device__ int    g_cursor[NL];
__device__ int    g_seg_start[NL + 1];
__device__ int    g_sorted[EE];
__device__ int    g_src_sorted[EE];

// pack two f32 -> f16x2 (lo = first arg)
__device__ __forceinline__ uint32_t h2pack(float lo, float hi) {
    uint32_t r;
    asm("cvt.rn.f16x2.f32 %0, %1, %2;" : "=r"(r) : "f"(hi), "f"(lo));
    return r;
}

// warp MMA: D[16x8] += A[16x16] * B[16x8]  fp16 in, fp32 acc  (row.col)
__device__ __forceinline__ void mma16(float (&d)[4], const uint32_t (&a)[4],
                                      uint32_t b0, uint32_t b1) {
    asm volatile(
        "mma.sync.aligned.m16n8k16.row.col.f32.f16.f16.f32 "
        "{%0,%1,%2,%3}, {%4,%5,%6,%7}, {%8,%9}, {%0,%1,%2,%3};"
        : "+f"(d[0]), "+f"(d[1]), "+f"(d[2]), "+f"(d[3])
        : "r"(a[0]), "r"(a[1]), "r"(a[2]), "r"(a[3]), "r"(b0), "r"(b1));
}

#define LDSM4(r0, r1, r2, r3, addr) \
    asm volatile("ldmatrix.sync.aligned.m8n8.x4.shared.b16 {%0,%1,%2,%3}, [%4];" \
                 : "=r"(r0), "=r"(r1), "=r"(r2), "=r"(r3) : "r"(addr))

// bulk async copy global->shared with mbarrier completion (sm_90 baseline)
#define BULKCP(dst, src, nbytes, mbar) \
    asm volatile("cp.async.bulk.shared::cluster.global.mbarrier::complete_tx::bytes " \
                 "[%0], [%1], %2, [%3];" \
                 :: "r"(dst), "l"(src), "r"(nbytes), "r"(mbar) : "memory")

#define MBAR_INIT(a, c) \
    asm volatile("mbarrier.init.shared.b64 [%0], %1;" :: "r"(a), "r"(c) : "memory")
#define MBAR_EXPECT(a, b) \
    asm volatile("mbarrier.arrive.expect_tx.shared.b64 _, [%0], %1;" :: "r"(a), "r"(b) : "memory")

__device__ __forceinline__ void mbar_wait(uint32_t mbar, uint32_t parity) {
    asm volatile(
        "{\n\t.reg .pred P1;\n\t"
        "WAIT_LOOP_%=:\n\t"
        "mbarrier.try_wait.parity.acquire.cta.shared::cta.b64 P1, [%0], %1, 0x989680;\n\t"
        "@P1 bra.uni WAIT_DONE_%=;\n\t"
        "bra.uni WAIT_LOOP_%=;\n\t"
        "WAIT_DONE_%=:\n\t}"
        :: "r"(mbar), "r"(parity) : "memory");
}

__device__ __forceinline__ uint32_t smem_u32(const void* p) {
    uint32_t a;
    asm("{ .reg .u64 t; cvta.to.shared.u64 t, %1; cvt.u32.u64 %0, t; }" : "=r"(a) : "l"(p));
    return a;
}
__device__ __forceinline__ uint64_t gmem_u64(const void* p) {
    uint64_t a;
    asm("cvta.to.global.u64 %0, %1;" : "=l"(a) : "l"(p));
    return a;
}

// ---------------------------------------------------------------------------
// Weight prep: transpose + fp16-round into pre-swizzled smem-image blocks.
// ---------------------------------------------------------------------------
__global__ void prep_kernel(const float* __restrict__ w1a, const float* __restrict__ w2a,
                            const float* __restrict__ w3a, const float* __restrict__ w1b,
                            const float* __restrict__ w2b, const float* __restrict__ w3b) {
    int id = blockIdx.x * 256 + threadIdx.x;
    if (id >= 6 * 49152) return;
    int m   = id / 98304;          // 0:w1, 1:w3, 2:w2
    int r   = id % 98304;
    int set = r / 49152;
    int q   = r % 49152;
    int c   = q / 16384;
    int a_  = (q / 128) % 128;     // n (or d)
    int k   = q % 128;             // k (or j)
    if (m < 2) {
        int n = a_;
        int img  = c * 2 + (n >> 6);
        int row  = n & 63;
        int colb = k * 2;
        int boff = ((row >> 3) + (colb >> 7) * 8) * 1024 + (row & 7) * 128
                 + ((colb & 127) ^ ((row & 7) * 16));
        const float* w = (m == 0) ? (set ? w1b : w1a) : (set ? w3b : w3a);
        __half* dst = (m == 0) ? g_w1h[set] : g_w3h[set];
        *(__half*)((char*)dst + (size_t)img * 16384 + boff) =
            __float2half_rn(w[k * HID + c * 128 + n]);
    } else {
        int d = a_, j = k;
        int img  = c * 2 + (j >> 6);
        int row  = d;
        int colb = (j & 63) * 2;
        int boff = (row >> 3) * 1024 + (row & 7) * 128 + (colb ^ ((row & 7) * 16));
        const float* w = set ? w2b : w2a;
        *(__half*)((char*)g_w2h[set] + (size_t)img * 16384 + boff) =
            __float2half_rn(w[(c * 128 + j) * DIM + d]);
    }
}

// ---------------------------------------------------------------------------
// fp16 mma.sync + ldmatrix fused gated FFN, 128-row tile, 256 threads/8 warps.
// Weight staging via cp.async.bulk. gemm1 is split into two ntp passes with
// TRANSIENT h/g accumulators (each pass: accumulate over K, silu, release) so
// peak register pressure stays well under the 255 cap (no spills).
//  MODE 0: reads param xin,  out = tanh(ffn(rmsnorm(x)) + x) -> g_vact
//  MODE 1: reads g_l, computes l2 = ffn(rmsnorm(l)) + l, then writes
//          out[row] = dot(l2, wout) + bout  (fused readout)
// ---------------------------------------------------------------------------
#define XS_OFF  0
#define WB_OFF  34816
#define WBUFS   49152
#define W1S     0
#define W3S     16384
#define W2S     32768
#define AS_OFF  133120
#define ASBS    18432
#define MB_OFF  169984
#define SMEM_TC 170240
#define XSTRH 136
#define ASTRH 72

template <int MODE>
__global__ void __launch_bounds__(256, 1) ffn_mma_kernel(
    const float* __restrict__ xin, const float* __restrict__ rw,
    const float* __restrict__ wout, const float* __restrict__ bout,
    float* __restrict__ out)
{
    extern __shared__ char smem[];
    const uint32_t sb = smem_u32(smem);

    const int tid  = threadIdx.x;
    const int lane = tid & 31;
    const int w    = tid >> 5;
    const int wy   = w >> 1;
    const int wx   = w & 1;
    const int gq   = lane >> 2;
    const int tg   = lane & 3;
    const int row0 = blockIdx.x * 128;

    const float* xbase = (MODE == 0) ? xin : g_l;
    const int set = (MODE == 0) ? 0 : 1;
    const uint64_t w1g = gmem_u64(g_w1h[set]);
    const uint64_t w3g = gmem_u64(g_w3h[set]);
    const uint64_t w2g = gmem_u64(g_w2h[set]);

    // ---- mbarrier init + stage chunk 0 into WB0 ----
    if (tid == 0) {
        MBAR_INIT(sb + MB_OFF,     1);
        MBAR_INIT(sb + MB_OFF + 8, 1);
    }
    __syncthreads();
    if (tid == 0) {
        MBAR_EXPECT(sb + MB_OFF, 49152u);
        BULKCP(sb + WB_OFF + W1S, w1g, 16384u, sb + MB_OFF);
        BULKCP(sb + WB_OFF + W3S, w3g, 16384u, sb + MB_OFF);
        BULKCP(sb + WB_OFF + W2S, w2g, 16384u, sb + MB_OFF);
    }

    // ---- load x tile + rmsnorm -> XS (f16); 2 threads per row ----
    {
        int r = tid >> 1, half = tid & 1;
        const float* xr = xbase + ((size_t)(row0 + r)) * DIM + half * 64;
        float vals[64];
        float ssq = 0.f;
        #pragma unroll
        for (int i = 0; i < 64; i += 4) {
            float4 v4 = *(const float4*)(xr + i);
            vals[i] = v4.x; vals[i+1] = v4.y; vals[i+2] = v4.z; vals[i+3] = v4.w;
            ssq += v4.x*v4.x + v4.y*v4.y + v4.z*v4.z + v4.w*v4.w;
        }
        ssq += __shfl_xor_sync(0xffffffffu, ssq, 1);
        float inv = rsqrtf(ssq * (1.0f / DIM) + EPS);
        uint32_t pk[32];
        #pragma unroll
        for (int i = 0; i < 32; i++) {
            float a0 = vals[2*i]     * inv * __ldg(rw + half * 64 + 2*i);
            float a1 = vals[2*i + 1] * inv * __ldg(rw + half * 64 + 2*i + 1);
            pk[i] = h2pack(a0, a1);
        }
        uint4* dst = (uint4*)(smem + XS_OFF + r * (XSTRH * 2) + half * 128);
        #pragma unroll
        for (int i = 0; i < 8; i++)
            dst[i] = make_uint4(pk[4*i], pk[4*i+1], pk[4*i+2], pk[4*i+3]);
    }

    // ---- warp-invariant ldmatrix lane addressing ----
    const int aRow = ((lane >> 3) & 1) * 8 + (lane & 7);
    const int aK   = (lane >> 4) * 8;
    const int bRow = ((lane >> 4) & 1) * 8 + (lane & 7);
    const int bK   = ((lane >> 3) & 1) * 8;
    const uint32_t ax0  = sb + XS_OFF + ((wy*32 +      aRow) * XSTRH + aK) * 2;
    const uint32_t ax1  = sb + XS_OFF + ((wy*32 + 16 + aRow) * XSTRH + aK) * 2;
    const uint32_t aas0 = sb + AS_OFF + ((wy*32 +      aRow) * ASTRH + aK) * 2;
    const uint32_t aas1 = sb + AS_OFF + ((wy*32 + 16 + aRow) * ASTRH + aK) * 2;
    const int colb0 = bK * 2;
    // gemm1 B rows (w1/w3 images, 64 rows x 256B, blocked atoms)
    uint32_t g1term[2], g1xm[2];
    #pragma unroll
    for (int ntp = 0; ntp < 2; ntp++) {
        int rn = wx * 32 + ntp * 16 + bRow;
        g1term[ntp] = (uint32_t)((rn >> 3) * 1024 + (rn & 7) * 128);
        g1xm[ntp]   = (uint32_t)((rn & 7) * 16);
    }
    // gemm2 B rows (w2 image, 128 rows x 128B)
    uint32_t g2term[4], g2xm[4];
    #pragma unroll
    for (int ntp = 0; ntp < 4; ntp++) {
        int rn = wx * 64 + ntp * 16 + bRow;
        g2term[ntp] = (uint32_t)((rn >> 3) * 1024 + (rn & 7) * 128);
        g2xm[ntp]   = (uint32_t)((rn & 7) * 16);
    }

    float Y[2][8][4];
    #pragma unroll
    for (int mt = 0; mt < 2; mt++)
        #pragma unroll
        for (int nt = 0; nt < 8; nt++)
            #pragma unroll
            for (int e = 0; e < 4; e++) Y[mt][nt][e] = 0.f;

    for (int cc = 0; cc < 6; cc++) {
        const uint32_t wb   = sb + WB_OFF + ((cc & 1) ? WBUFS : 0u);
        const uint32_t asel = (cc & 1) ? ASBS : 0u;

        // wait for this buffer's staging; parity = (cc>>1)&1
        mbar_wait(sb + MB_OFF + (cc & 1) * 8, (uint32_t)((cc >> 1) & 1));
        __syncthreads();   // all warps done with chunk cc-1 (buffer reuse safe)

        // ---- stage chunk cc+1 into the other buffer (3 bulk copies) ----
        if (cc < 5 && tid == 0) {
            uint32_t mb = sb + MB_OFF + ((cc + 1) & 1) * 8;
            uint32_t ob = sb + WB_OFF + (((cc + 1) & 1) ? WBUFS : 0u);
            uint64_t off = (uint64_t)(cc + 1) * 16384u;
            MBAR_EXPECT(mb, 49152u);
            BULKCP(ob + W1S, w1g + off, 16384u, mb);
            BULKCP(ob + W3S, w3g + off, 16384u, mb);
            BULKCP(ob + W2S, w2g + off, 16384u, mb);
        }

        // ---- gemm1 + silu, two ntp passes with transient accumulators ----
        uint32_t* asu = (uint32_t*)(smem + AS_OFF + asel);
        #pragma unroll
        for (int ntp = 0; ntp < 2; ntp++) {
            float h[2][2][4], gg[2][2][4];     // [mt][sub]
            #pragma unroll
            for (int mt = 0; mt < 2; mt++)
                #pragma unroll
                for (int s_ = 0; s_ < 2; s_++)
                    #pragma unroll
                    for (int e = 0; e < 4; e++) { h[mt][s_][e] = 0.f; gg[mt][s_][e] = 0.f; }

            #pragma unroll
            for (int ks = 0; ks < 8; ks++) {
                uint32_t af[2][4];
                LDSM4(af[0][0], af[0][1], af[0][2], af[0][3], ax0 + ks * 32);
                LDSM4(af[1][0], af[1][1], af[1][2], af[1][3], ax1 + ks * 32);
                const int colb = colb0 + ks * 32;
                const uint32_t aoff = ((uint32_t)(colb & 128) << 6)
                                    + (((uint32_t)(colb & 127)) ^ g1xm[ntp]) + g1term[ntp];
                uint32_t b1f[4], b3f[4];
                LDSM4(b1f[0], b1f[1], b1f[2], b1f[3], wb + W1S + aoff);
                LDSM4(b3f[0], b3f[1], b3f[2], b3f[3], wb + W3S + aoff);
                #pragma unroll
                for (int mt = 0; mt < 2; mt++) {
                    mma16(h[mt][0],  af[mt], b1f[0], b1f[1]);
                    mma16(h[mt][1],  af[mt], b1f[2], b1f[3]);
                    mma16(gg[mt][0], af[mt], b3f[0], b3f[1]);
                    mma16(gg[mt][1], af[mt], b3f[2], b3f[3]);
                }
            }

            // silu epilogue for nt = 2*ntp + sub (releases h/gg)
            #pragma unroll
            for (int mt = 0; mt < 2; mt++) {
                #pragma unroll
                for (int s_ = 0; s_ < 2; s_++) {
                    int nt = 2 * ntp + s_;
                    int r  = wy * 32 + mt * 16 + gq;
                    int cu = wx * 16 + nt * 4 + tg;        // u32 column
                    float h0 = h[mt][s_][0], h1 = h[mt][s_][1];
                    float h2_ = h[mt][s_][2], h3 = h[mt][s_][3];
                    float a0 = h0 / (1.f + __expf(-h0)) * gg[mt][s_][0];
                    float a1 = h1 / (1.f + __expf(-h1)) * gg[mt][s_][1];
                    float a2 = h2_ / (1.f + __expf(-h2_)) * gg[mt][s_][2];
                    float a3 = h3 / (1.f + __expf(-h3)) * gg[mt][s_][3];
                    asu[r * 36 + cu]       = h2pack(a0, a1);
                    asu[(r + 8) * 36 + cu] = h2pack(a2, a3);
                }
            }
        }
        // only the two warps of this M slab exchange AS rows
        asm volatile("bar.sync %0, 64;" :: "r"(wy + 1) : "memory");

        // ---- gemm2: Y += a @ w2c (warp tile 32x64, K=64) ----
        #pragma unroll
        for (int ks = 0; ks < 4; ks++) {
            uint32_t af[2][4];
            LDSM4(af[0][0], af[0][1], af[0][2], af[0][3], aas0 + asel + ks * 32);
            LDSM4(af[1][0], af[1][1], af[1][2], af[1][3], aas1 + asel + ks * 32);
            const uint32_t cinn2 = (uint32_t)(colb0 + ks * 32);   // < 128
            #pragma unroll
            for (int ntp = 0; ntp < 4; ntp++) {
                uint32_t bf[4];
                uint32_t aoff = g2term[ntp] + (cinn2 ^ g2xm[ntp]);
                LDSM4(bf[0], bf[1], bf[2], bf[3], wb + W2S + aoff);
                #pragma unroll
                for (int mt = 0; mt < 2; mt++) {
                    mma16(Y[mt][2*ntp],   af[mt], bf[0], bf[1]);
                    mma16(Y[mt][2*ntp+1], af[mt], bf[2], bf[3]);
                }
            }
        }
    }
    __syncthreads();

    // ---- stage Y (f32, stride 132) into smem [0..67584) ----
    float* xsf = (float*)smem;
    #pragma unroll
    for (int mt = 0; mt < 2; mt++) {
        #pragma unroll
        for (int nt = 0; nt < 8; nt++) {
            int r   = wy * 32 + mt * 16 + gq;
            int col = wx * 64 + nt * 8 + tg * 2;
            *(float2*)(xsf + r * 132 + col)       = make_float2(Y[mt][nt][0], Y[mt][nt][1]);
            *(float2*)(xsf + (r + 8) * 132 + col) = make_float2(Y[mt][nt][2], Y[mt][nt][3]);
        }
    }
    __syncthreads();
    {
        int r = tid >> 1, half = tid & 1;
        const float* resr = xbase + ((size_t)(row0 + r)) * DIM + half * 64;
        const float* yr   = xsf + r * 132 + half * 64;
        if (MODE == 0) {
            float* outr = g_vact + ((size_t)(row0 + r)) * DIM + half * 64;
            #pragma unroll
            for (int i = 0; i < 64; i += 4) {
                float4 y4 = *(const float4*)(yr + i);
                float4 r4 = *(const float4*)(resr + i);
                float4 o;
                o.x = tanhf(y4.x + r4.x); o.y = tanhf(y4.y + r4.y);
                o.z = tanhf(y4.z + r4.z); o.w = tanhf(y4.w + r4.w);
                *(float4*)(outr + i) = o;
            }
        } else {
            // fused readout: out[row] = dot(y + l, wout) + bout
            float acc = 0.f;
            #pragma unroll
            for (int i = 0; i < 64; i += 4) {
                float4 y4 = *(const float4*)(yr + i);
                float4 r4 = *(const float4*)(resr + i);
                float4 w4 = *(const float4*)(wout + half * 64 + i);
                acc += (y4.x + r4.x) * w4.x + (y4.y + r4.y) * w4.y
                     + (y4.z + r4.z) * w4.z + (y4.w + r4.w) * w4.w;
            }
            acc += __shfl_xor_sync(0xffffffffu, acc, 1);
            if (half == 0) out[row0 + r] = acc + bout[0];
        }
    }
}

// ---------------------------------------------------------------------------
// Segment machinery: histogram -> scan -> scatter -> sort -> product
// ---------------------------------------------------------------------------
__global__ void init_hist_kernel() {
    int i = blockIdx.x * blockDim.x + threadIdx.x;
    if (i < NL) g_hist[i] = 0;
}
__global__ void hist_kernel(const int* __restrict__ dd) {
    int e = blockIdx.x * blockDim.x + threadIdx.x;
    if (e < EE) atomicAdd(&g_hist[dd[e]], 1);
}
__global__ void scan_kernel() {
    __shared__ int sdata[1024];
    int tid = threadIdx.x;
    int base = tid * 4;
    int s0 = g_hist[base], s1 = g_hist[base+1], s2 = g_hist[base+2], s3 = g_hist[base+3];
    int tsum = s0 + s1 + s2 + s3;
    sdata[tid] = tsum;
    __syncthreads();
    for (int off = 1; off < 1024; off <<= 1) {
        int v_ = sdata[tid];
        int u  = (tid >= off) ? sdata[tid - off] : 0;
        __syncthreads();
        sdata[tid] = v_ + u;
        __syncthreads();
    }
    int excl = sdata[tid] - tsum;
    int o0 = excl, o1 = excl + s0, o2 = excl + s0 + s1, o3 = excl + s0 + s1 + s2;
    g_seg_start[base]   = o0;  g_cursor[base]   = o0;
    g_seg_start[base+1] = o1;  g_cursor[base+1] = o1;
    g_seg_start[base+2] = o2;  g_cursor[base+2] = o2;
    g_seg_start[base+3] = o3;  g_cursor[base+3] = o3;
    if (tid == 1023) g_seg_start[NL] = sdata[1023];
}
__global__ void scatter_kernel(const int* __restrict__ dd) {
    int e = blockIdx.x * blockDim.x + threadIdx.x;
    if (e < EE) {
        int pos = atomicAdd(&g_cursor[dd[e]], 1);
        g_sorted[pos] = e;
    }
}

// one 256-thread block per segment: odd-even sort edge ids (deterministic
// order), then materialize g_src_sorted = data_src[sorted ids].
__global__ void __launch_bounds__(256) seg_sort_kernel(const int* __restrict__ ds) {
    __shared__ int sidx[512];
    int s = blockIdx.x, tid = threadIdx.x;
    int start = g_seg_start[s], end = g_seg_start[s + 1];
    int n = end - start;
    if (n <= 512) {
        for (int i = tid; i < n; i += 256) sidx[i] = g_sorted[start + i];
        __syncthreads();
        for (int pass = 0; pass < n; pass++) {
            int i = 2 * tid + (pass & 1);
            if (i + 1 < n) {
                int a = sidx[i], bb = sidx[i + 1];
                if (a > bb) { sidx[i] = bb; sidx[i + 1] = a; }
            }
            __syncthreads();
        }
        for (int i = tid; i < n; i += 256) g_src_sorted[start + i] = ds[sidx[i]];
    } else {
        for (int i = tid; i < n; i += 256) g_src_sorted[start + i] = ds[g_sorted[start + i]];
    }
}

// one block per segment, 512 threads = 4 batches x 128 dims, pure gather
__global__ void __launch_bounds__(512) segprod_kernel() {
    __shared__ int ssrc[512];
    int s   = blockIdx.x;
    int tid = threadIdx.x;
    int b   = tid >> 7;
    int d   = tid & 127;
    int start = g_seg_start[s], end = g_seg_start[s + 1];
    int n = end - start;
    float p[16];
    #pragma unroll
    for (int j = 0; j < 16; j++) p[j] = 1.f;
    const float* vb = g_vact + (size_t)b * ND * DIM + d;

    for (int base = 0; base < n; base += 512) {
        int cnt = min(512, n - base);
        __syncthreads();
        if (tid < cnt) ssrc[tid] = g_src_sorted[start + base + tid];
        __syncthreads();
        int i = 0;
        for (; i + 16 <= cnt; i += 16) {
            #pragma unroll
            for (int j = 0; j < 16; j++)
                p[j] *= vb[(size_t)ssrc[i + j] * DIM];
        }
        for (; i + 4 <= cnt; i += 4) {
            p[0] *= vb[(size_t)ssrc[i]     * DIM];
            p[1] *= vb[(size_t)ssrc[i + 1] * DIM];
            p[2] *= vb[(size_t)ssrc[i + 2] * DIM];
            p[3] *= vb[(size_t)ssrc[i + 3] * DIM];
        }
        for (; i < cnt; i++) p[0] *= vb[(size_t)ssrc[i] * DIM];
    }
    float r = ((p[0]*p[1]) * (p[2]*p[3])) * ((p[4]*p[5]) * (p[6]*p[7]));
    r *= ((p[8]*p[9]) * (p[10]*p[11])) * ((p[12]*p[13]) * (p[14]*p[15]));
    g_l[((size_t)b * NL + s) * DIM + d] = r;
}

// ---------------------------------------------------------------------------
extern "C" void kernel_launch(void* const* d_in, const int* in_sizes, int n_in,
                              void* d_out, int out_size)
{
    const float* v        = (const float*)d_in[0];
    const int*   data_src = (const int*)  d_in[1];
    const int*   data_dst = (const int*)  d_in[2];
    int base = (n_in >= 14 && in_sizes[3] == 1) ? 4 : 3;
    const float* rms1_w = (const float*)d_in[base + 0];
    const float* w1a    = (const float*)d_in[base + 1];
    const float* w2a    = (const float*)d_in[base + 2];
    const float* w3a    = (const float*)d_in[base + 3];
    const float* rms2_w = (const float*)d_in[base + 4];
    const float* w1b    = (const float*)d_in[base + 5];
    const float* w2b    = (const float*)d_in[base + 6];
    const float* w3b    = (const float*)d_in[base + 7];
    const float* wout   = (const float*)d_in[base + 8];
    const float* bout   = (const float*)d_in[base + 9];
    float* out = (float*)d_out;

    cudaFuncSetAttribute(ffn_mma_kernel<0>, cudaFuncAttributeMaxDynamicSharedMemorySize, SMEM_TC);
    cudaFuncSetAttribute(ffn_mma_kernel<1>, cudaFuncAttributeMaxDynamicSharedMemorySize, SMEM_TC);

    // Fork the bucketing chain onto a side stream; issue order keeps ffn1 as
    // launch #4 (ncu capture slot): init_hist(1), hist(2) [side]; prep(3),
    // ffn1(4) [main]; scan(5), scatter(6), seg_sort(7) [side]; join; segprod; ffn2.
    cudaStream_t s2 = nullptr;
    cudaEvent_t evFork = nullptr, evJoin = nullptr;
    bool par = (cudaStreamCreateWithFlags(&s2, cudaStreamNonBlocking) == cudaSuccess);
    if (par) par = (cudaEventCreateWithFlags(&evFork, cudaEventDisableTiming) == cudaSuccess);
    if (par) par = (cudaEventCreateWithFlags(&evJoin, cudaEventDisableTiming) == cudaSuccess);

    cudaStream_t bs = par ? s2 : (cudaStream_t)0;

    if (par) {
        cudaEventRecord(evFork, 0);
        cudaStreamWaitEvent(s2, evFork, 0);
    }

    init_hist_kernel<<<(NL + 255) / 256, 256, 0, bs>>>();
    hist_kernel<<<(EE + 1023) / 1024, 1024, 0, bs>>>(data_dst);

    prep_kernel<<<(6 * 49152 + 255) / 256, 256>>>(w1a, w2a, w3a, w1b, w2b, w3b);
    ffn_mma_kernel<0><<<NTOK / 128, 256, SMEM_TC>>>(v, rms1_w, nullptr, nullptr, nullptr);

    scan_kernel<<<1, 1024, 0, bs>>>();
    scatter_kernel<<<(EE + 1023) / 1024, 1024, 0, bs>>>(data_dst);
    seg_sort_kernel<<<NL, 256, 0, bs>>>(data_src);

    if (par) {
        cudaEventRecord(evJoin, s2);
        cudaStreamWaitEvent((cudaStream_t)0, evJoin, 0);
    }

    segprod_kernel<<<NL, 512>>>();
    ffn_mma_kernel<1><<<(BB * NL) / 128, 256, SMEM_TC>>>(nullptr, rms2_w, wout, bout, out);
}

// round 17
// speedup vs baseline: 1.0414x; 1.0414x over previous
#include <cuda_runtime.h>
#include <cuda_fp16.h>
#include <cstdint>
#include <math.h>

#define DIM   128
#define HID   384
#define BB    4
#define ND    100000
#define NTOK  400000
#define NL    4096
#define EE    200000
#define EPS   1e-5f

// ---------------- scratch (device globals; no allocations allowed) ----------
// NOTE: reference these symbols ONLY from device code (Round-5 ATS lesson).
__device__ float  g_vact[(size_t)NTOK * DIM];       // 204.8 MB
__device__ float  g_l[(size_t)BB * NL * DIM];       // 8.4 MB
// Weights stored as pre-swizzled 16KB smem-image blocks, one per (c, n0half):
// img index = c*2 + n0half, 6 images of 8192 halfs per set.
__device__ __half g_w1h[2][6 * 8192];
__device__ __half g_w3h[2][6 * 8192];
__device__ __half g_w2h[2][6 * 8192];
__device__ int    g_hist[NL];
__device__ int    g_cursor[NL];
__device__ int    g_seg_start[NL + 1];
__device__ int    g_sorted[EE];
__device__ int    g_src_sorted[EE];

// pack two f32 -> f16x2 (lo = first arg)
__device__ __forceinline__ uint32_t h2pack(float lo, float hi) {
    uint32_t r;
    asm("cvt.rn.f16x2.f32 %0, %1, %2;" : "=r"(r) : "f"(hi), "f"(lo));
    return r;
}

// warp MMA: D[16x8] += A[16x16] * B[16x8]  fp16 in, fp32 acc  (row.col)
__device__ __forceinline__ void mma16(float (&d)[4], const uint32_t (&a)[4],
                                      uint32_t b0, uint32_t b1) {
    asm volatile(
        "mma.sync.aligned.m16n8k16.row.col.f32.f16.f16.f32 "
        "{%0,%1,%2,%3}, {%4,%5,%6,%7}, {%8,%9}, {%0,%1,%2,%3};"
        : "+f"(d[0]), "+f"(d[1]), "+f"(d[2]), "+f"(d[3])
        : "r"(a[0]), "r"(a[1]), "r"(a[2]), "r"(a[3]), "r"(b0), "r"(b1));
}

#define LDSM4(r0, r1, r2, r3, addr) \
    asm volatile("ldmatrix.sync.aligned.m8n8.x4.shared.b16 {%0,%1,%2,%3}, [%4];" \
                 : "=r"(r0), "=r"(r1), "=r"(r2), "=r"(r3) : "r"(addr))

// bulk async copy global->shared with mbarrier completion (sm_90 baseline)
#define BULKCP(dst, src, nbytes, mbar) \
    asm volatile("cp.async.bulk.shared::cluster.global.mbarrier::complete_tx::bytes " \
                 "[%0], [%1], %2, [%3];" \
                 :: "r"(dst), "l"(src), "r"(nbytes), "r"(mbar) : "memory")

#define MBAR_INIT(a, c) \
    asm volatile("mbarrier.init.shared.b64 [%0], %1;" :: "r"(a), "r"(c) : "memory")
#define MBAR_EXPECT(a, b) \
    asm volatile("mbarrier.arrive.expect_tx.shared.b64 _, [%0], %1;" :: "r"(a), "r"(b) : "memory")

__device__ __forceinline__ void mbar_wait(uint32_t mbar, uint32_t parity) {
    asm volatile(
        "{\n\t.reg .pred P1;\n\t"
        "WAIT_LOOP_%=:\n\t"
        "mbarrier.try_wait.parity.acquire.cta.shared::cta.b64 P1, [%0], %1, 0x989680;\n\t"
        "@P1 bra.uni WAIT_DONE_%=;\n\t"
        "bra.uni WAIT_LOOP_%=;\n\t"
        "WAIT_DONE_%=:\n\t}"
        :: "r"(mbar), "r"(parity) : "memory");
}

__device__ __forceinline__ uint32_t smem_u32(const void* p) {
    uint32_t a;
    asm("{ .reg .u64 t; cvta.to.shared.u64 t, %1; cvt.u32.u64 %0, t; }" : "=r"(a) : "l"(p));
    return a;
}
__device__ __forceinline__ uint64_t gmem_u64(const void* p) {
    uint64_t a;
    asm("cvta.to.global.u64 %0, %1;" : "=l"(a) : "l"(p));
    return a;
}

// ---------------------------------------------------------------------------
// Weight prep: transpose + fp16-round into pre-swizzled smem-image blocks.
// ---------------------------------------------------------------------------
__global__ void prep_kernel(const float* __restrict__ w1a, const float* __restrict__ w2a,
                            const float* __restrict__ w3a, const float* __restrict__ w1b,
                            const float* __restrict__ w2b, const float* __restrict__ w3b) {
    int id = blockIdx.x * 256 + threadIdx.x;
    if (id >= 6 * 49152) return;
    int m   = id / 98304;          // 0:w1, 1:w3, 2:w2
    int r   = id % 98304;
    int set = r / 49152;
    int q   = r % 49152;
    int c   = q / 16384;
    int a_  = (q / 128) % 128;     // n (or d)
    int k   = q % 128;             // k (or j)
    if (m < 2) {
        int n = a_;
        int img  = c * 2 + (n >> 6);
        int row  = n & 63;
        int colb = k * 2;
        int boff = ((row >> 3) + (colb >> 7) * 8) * 1024 + (row & 7) * 128
                 + ((colb & 127) ^ ((row & 7) * 16));
        const float* w = (m == 0) ? (set ? w1b : w1a) : (set ? w3b : w3a);
        __half* dst = (m == 0) ? g_w1h[set] : g_w3h[set];
        *(__half*)((char*)dst + (size_t)img * 16384 + boff) =
            __float2half_rn(w[k * HID + c * 128 + n]);
    } else {
        int d = a_, j = k;
        int img  = c * 2 + (j >> 6);
        int row  = d;
        int colb = (j & 63) * 2;
        int boff = (row >> 3) * 1024 + (row & 7) * 128 + (colb ^ ((row & 7) * 16));
        const float* w = set ? w2b : w2a;
        *(__half*)((char*)g_w2h[set] + (size_t)img * 16384 + boff) =
            __float2half_rn(w[(c * 128 + j) * DIM + d]);
    }
}

// ---------------------------------------------------------------------------
// fp16 mma.sync + ldmatrix fused gated FFN, 128-row tile, 512 threads/16 warps
// (4 warps/SMSP for latency hiding). Weight staging via cp.async.bulk into
// double-buffered pre-swizzled images. Warp = 16-row M slab x 64-col N half.
//  MODE 0: reads param xin,  out = tanh(ffn(rmsnorm(x)) + x) -> g_vact
//  MODE 1: reads g_l, computes l2 = ffn(rmsnorm(l)) + l, then writes
//          out[row] = dot(l2, wout) + bout  (fused readout)
// ---------------------------------------------------------------------------
#define XS_OFF  0
#define WB_OFF  34816
#define WBUFS   49152
#define W1S     0
#define W3S     16384
#define W2S     32768
#define AS_OFF  133120
#define ASBS    18432
#define MB_OFF  169984
#define SMEM_TC 170240
#define XSTRH 136
#define ASTRH 72

template <int MODE>
__global__ void __launch_bounds__(512, 1) ffn_mma_kernel(
    const float* __restrict__ xin, const float* __restrict__ rw,
    const float* __restrict__ wout, const float* __restrict__ bout,
    float* __restrict__ out)
{
    extern __shared__ char smem[];
    const uint32_t sb = smem_u32(smem);

    const int tid  = threadIdx.x;
    const int lane = tid & 31;
    const int w    = tid >> 5;    // 0..15
    const int wy   = w >> 1;      // 0..7  (16-row M slab)
    const int wx   = w & 1;       // 0..1  (N half)
    const int gq   = lane >> 2;
    const int tg   = lane & 3;
    const int row0 = blockIdx.x * 128;

    const float* xbase = (MODE == 0) ? xin : g_l;
    const int set = (MODE == 0) ? 0 : 1;
    const uint64_t w1g = gmem_u64(g_w1h[set]);
    const uint64_t w3g = gmem_u64(g_w3h[set]);
    const uint64_t w2g = gmem_u64(g_w2h[set]);

    // ---- mbarrier init + stage chunk 0 into WB0 ----
    if (tid == 0) {
        MBAR_INIT(sb + MB_OFF,     1);
        MBAR_INIT(sb + MB_OFF + 8, 1);
    }
    __syncthreads();
    if (tid == 0) {
        MBAR_EXPECT(sb + MB_OFF, 49152u);
        BULKCP(sb + WB_OFF + W1S, w1g, 16384u, sb + MB_OFF);
        BULKCP(sb + WB_OFF + W3S, w3g, 16384u, sb + MB_OFF);
        BULKCP(sb + WB_OFF + W2S, w2g, 16384u, sb + MB_OFF);
    }

    // ---- load x tile + rmsnorm -> XS (f16); 4 threads per row ----
    {
        int r = tid >> 2, q4 = tid & 3;
        const float* xr = xbase + ((size_t)(row0 + r)) * DIM + q4 * 32;
        float vals[32];
        float ssq = 0.f;
        #pragma unroll
        for (int i = 0; i < 32; i += 4) {
            float4 v4 = *(const float4*)(xr + i);
            vals[i] = v4.x; vals[i+1] = v4.y; vals[i+2] = v4.z; vals[i+3] = v4.w;
            ssq += v4.x*v4.x + v4.y*v4.y + v4.z*v4.z + v4.w*v4.w;
        }
        ssq += __shfl_xor_sync(0xffffffffu, ssq, 1);
        ssq += __shfl_xor_sync(0xffffffffu, ssq, 2);
        float inv = rsqrtf(ssq * (1.0f / DIM) + EPS);
        uint32_t pk[16];
        #pragma unroll
        for (int i = 0; i < 16; i++) {
            float a0 = vals[2*i]     * inv * __ldg(rw + q4 * 32 + 2*i);
            float a1 = vals[2*i + 1] * inv * __ldg(rw + q4 * 32 + 2*i + 1);
            pk[i] = h2pack(a0, a1);
        }
        uint4* dst = (uint4*)(smem + XS_OFF + r * (XSTRH * 2) + q4 * 64);
        #pragma unroll
        for (int i = 0; i < 4; i++)
            dst[i] = make_uint4(pk[4*i], pk[4*i+1], pk[4*i+2], pk[4*i+3]);
    }

    // ---- warp-invariant ldmatrix lane addressing ----
    const int aRow = ((lane >> 3) & 1) * 8 + (lane & 7);
    const int aK   = (lane >> 4) * 8;
    const int bRow = ((lane >> 4) & 1) * 8 + (lane & 7);
    const int bK   = ((lane >> 3) & 1) * 8;
    const uint32_t ax0  = sb + XS_OFF + ((wy*16 + aRow) * XSTRH + aK) * 2;
    const uint32_t aas0 = sb + AS_OFF + ((wy*16 + aRow) * ASTRH + aK) * 2;
    const int colb0 = bK * 2;
    // gemm1 B rows (w1/w3 images, 64 rows x 256B, blocked atoms)
    uint32_t g1term[2], g1xm[2];
    #pragma unroll
    for (int ntp = 0; ntp < 2; ntp++) {
        int rn = wx * 32 + ntp * 16 + bRow;
        g1term[ntp] = (uint32_t)((rn >> 3) * 1024 + (rn & 7) * 128);
        g1xm[ntp]   = (uint32_t)((rn & 7) * 16);
    }
    // gemm2 B rows (w2 image, 128 rows x 128B)
    uint32_t g2term[4], g2xm[4];
    #pragma unroll
    for (int ntp = 0; ntp < 4; ntp++) {
        int rn = wx * 64 + ntp * 16 + bRow;
        g2term[ntp] = (uint32_t)((rn >> 3) * 1024 + (rn & 7) * 128);
        g2xm[ntp]   = (uint32_t)((rn & 7) * 16);
    }

    float Y[8][4];
    #pragma unroll
    for (int nt = 0; nt < 8; nt++)
        #pragma unroll
        for (int e = 0; e < 4; e++) Y[nt][e] = 0.f;

    for (int cc = 0; cc < 6; cc++) {
        const uint32_t wb   = sb + WB_OFF + ((cc & 1) ? WBUFS : 0u);
        const uint32_t asel = (cc & 1) ? ASBS : 0u;

        // wait for this buffer's staging; parity = (cc>>1)&1
        mbar_wait(sb + MB_OFF + (cc & 1) * 8, (uint32_t)((cc >> 1) & 1));
        __syncthreads();   // all warps done with chunk cc-1 (buffer reuse safe)

        // ---- stage chunk cc+1 into the other buffer (3 bulk copies) ----
        if (cc < 5 && tid == 0) {
            uint32_t mb = sb + MB_OFF + ((cc + 1) & 1) * 8;
            uint32_t ob = sb + WB_OFF + (((cc + 1) & 1) ? WBUFS : 0u);
            uint64_t off = (uint64_t)(cc + 1) * 16384u;
            MBAR_EXPECT(mb, 49152u);
            BULKCP(ob + W1S, w1g + off, 16384u, mb);
            BULKCP(ob + W3S, w3g + off, 16384u, mb);
            BULKCP(ob + W2S, w2g + off, 16384u, mb);
        }

        // ---- gemm1 + silu, two ntp passes with transient accumulators ----
        // warp tile 16 rows x 32 cols, K=128
        uint32_t* asu = (uint32_t*)(smem + AS_OFF + asel);
        #pragma unroll
        for (int ntp = 0; ntp < 2; ntp++) {
            float h[2][4], gg[2][4];     // [sub n-tile]
            #pragma unroll
            for (int s_ = 0; s_ < 2; s_++)
                #pragma unroll
                for (int e = 0; e < 4; e++) { h[s_][e] = 0.f; gg[s_][e] = 0.f; }

            #pragma unroll
            for (int ks = 0; ks < 8; ks++) {
                uint32_t af[4];
                LDSM4(af[0], af[1], af[2], af[3], ax0 + ks * 32);
                const int colb = colb0 + ks * 32;
                const uint32_t aoff = ((uint32_t)(colb & 128) << 6)
                                    + (((uint32_t)(colb & 127)) ^ g1xm[ntp]) + g1term[ntp];
                uint32_t b1f[4], b3f[4];
                LDSM4(b1f[0], b1f[1], b1f[2], b1f[3], wb + W1S + aoff);
                LDSM4(b3f[0], b3f[1], b3f[2], b3f[3], wb + W3S + aoff);
                mma16(h[0],  af, b1f[0], b1f[1]);
                mma16(h[1],  af, b1f[2], b1f[3]);
                mma16(gg[0], af, b3f[0], b3f[1]);
                mma16(gg[1], af, b3f[2], b3f[3]);
            }

            // silu epilogue for nt = 2*ntp + sub (releases h/gg)
            #pragma unroll
            for (int s_ = 0; s_ < 2; s_++) {
                int nt = 2 * ntp + s_;
                int r  = wy * 16 + gq;
                int cu = wx * 16 + nt * 4 + tg;        // u32 column
                float h0 = h[s_][0], h1 = h[s_][1];
                float h2_ = h[s_][2], h3 = h[s_][3];
                float a0 = h0 / (1.f + __expf(-h0)) * gg[s_][0];
                float a1 = h1 / (1.f + __expf(-h1)) * gg[s_][1];
                float a2 = h2_ / (1.f + __expf(-h2_)) * gg[s_][2];
                float a3 = h3 / (1.f + __expf(-h3)) * gg[s_][3];
                asu[r * 36 + cu]       = h2pack(a0, a1);
                asu[(r + 8) * 36 + cu] = h2pack(a2, a3);
            }
        }
        // only the two warps of this M slab exchange AS rows
        asm volatile("bar.sync %0, 64;" :: "r"(wy + 1) : "memory");

        // ---- gemm2: Y += a @ w2c (warp tile 16x64, K=64) ----
        #pragma unroll
        for (int ks = 0; ks < 4; ks++) {
            uint32_t af[4];
            LDSM4(af[0], af[1], af[2], af[3], aas0 + asel + ks * 32);
            const uint32_t cinn2 = (uint32_t)(colb0 + ks * 32);   // < 128
            #pragma unroll
            for (int ntp = 0; ntp < 4; ntp++) {
                uint32_t bf[4];
                uint32_t aoff = g2term[ntp] + (cinn2 ^ g2xm[ntp]);
                LDSM4(bf[0], bf[1], bf[2], bf[3], wb + W2S + aoff);
                mma16(Y[2*ntp],   af, bf[0], bf[1]);
                mma16(Y[2*ntp+1], af, bf[2], bf[3]);
            }
        }
    }
    __syncthreads();

    // ---- stage Y (f32, stride 132) into smem [0..67584) ----
    float* xsf = (float*)smem;
    #pragma unroll
    for (int nt = 0; nt < 8; nt++) {
        int r   = wy * 16 + gq;
        int col = wx * 64 + nt * 8 + tg * 2;
        *(float2*)(xsf + r * 132 + col)       = make_float2(Y[nt][0], Y[nt][1]);
        *(float2*)(xsf + (r + 8) * 132 + col) = make_float2(Y[nt][2], Y[nt][3]);
    }
    __syncthreads();
    {
        int r = tid >> 2, q4 = tid & 3;
        int row = row0 + r;
        const float* resr = xbase + ((size_t)row) * DIM + q4 * 32;
        const float* yr   = xsf + r * 132 + q4 * 32;
        if (MODE == 0) {
            float* outr = g_vact + ((size_t)row) * DIM + q4 * 32;
            #pragma unroll
            for (int i = 0; i < 32; i += 4) {
                float4 y4 = *(const float4*)(yr + i);
                float4 r4 = *(const float4*)(resr + i);
                float4 o;
                o.x = tanhf(y4.x + r4.x); o.y = tanhf(y4.y + r4.y);
                o.z = tanhf(y4.z + r4.z); o.w = tanhf(y4.w + r4.w);
                *(float4*)(outr + i) = o;
            }
        } else {
            // fused readout: out[row] = dot(y + l, wout) + bout
            float acc = 0.f;
            #pragma unroll
            for (int i = 0; i < 32; i += 4) {
                float4 y4 = *(const float4*)(yr + i);
                float4 r4 = *(const float4*)(resr + i);
                float4 w4 = *(const float4*)(wout + q4 * 32 + i);
                acc += (y4.x + r4.x) * w4.x + (y4.y + r4.y) * w4.y
                     + (y4.z + r4.z) * w4.z + (y4.w + r4.w) * w4.w;
            }
            acc += __shfl_xor_sync(0xffffffffu, acc, 1);
            acc += __shfl_xor_sync(0xffffffffu, acc, 2);
            if (q4 == 0) out[row] = acc + bout[0];
        }
    }
}

// ---------------------------------------------------------------------------
// Segment machinery: histogram -> scan -> scatter -> sort -> product
// ---------------------------------------------------------------------------
__global__ void init_hist_kernel() {
    int i = blockIdx.x * blockDim.x + threadIdx.x;
    if (i < NL) g_hist[i] = 0;
}
__global__ void hist_kernel(const int* __restrict__ dd) {
    int e = blockIdx.x * blockDim.x + threadIdx.x;
    if (e < EE) atomicAdd(&g_hist[dd[e]], 1);
}
__global__ void scan_kernel() {
    __shared__ int sdata[1024];
    int tid = threadIdx.x;
    int base = tid * 4;
    int s0 = g_hist[base], s1 = g_hist[base+1], s2 = g_hist[base+2], s3 = g_hist[base+3];
    int tsum = s0 + s1 + s2 + s3;
    sdata[tid] = tsum;
    __syncthreads();
    for (int off = 1; off < 1024; off <<= 1) {
        int v_ = sdata[tid];
        int u  = (tid >= off) ? sdata[tid - off] : 0;
        __syncthreads();
        sdata[tid] = v_ + u;
        __syncthreads();
    }
    int excl = sdata[tid] - tsum;
    int o0 = excl, o1 = excl + s0, o2 = excl + s0 + s1, o3 = excl + s0 + s1 + s2;
    g_seg_start[base]   = o0;  g_cursor[base]   = o0;
    g_seg_start[base+1] = o1;  g_cursor[base+1] = o1;
    g_seg_start[base+2] = o2;  g_cursor[base+2] = o2;
    g_seg_start[base+3] = o3;  g_cursor[base+3] = o3;
    if (tid == 1023) g_seg_start[NL] = sdata[1023];
}
__global__ void scatter_kernel(const int* __restrict__ dd) {
    int e = blockIdx.x * blockDim.x + threadIdx.x;
    if (e < EE) {
        int pos = atomicAdd(&g_cursor[dd[e]], 1);
        g_sorted[pos] = e;
    }
}

// one 256-thread block per segment: odd-even sort edge ids (deterministic
// order), then materialize g_src_sorted = data_src[sorted ids].
__global__ void __launch_bounds__(256) seg_sort_kernel(const int* __restrict__ ds) {
    __shared__ int sidx[512];
    int s = blockIdx.x, tid = threadIdx.x;
    int start = g_seg_start[s], end = g_seg_start[s + 1];
    int n = end - start;
    if (n <= 512) {
        for (int i = tid; i < n; i += 256) sidx[i] = g_sorted[start + i];
        __syncthreads();
        for (int pass = 0; pass < n; pass++) {
            int i = 2 * tid + (pass & 1);
            if (i + 1 < n) {
                int a = sidx[i], bb = sidx[i + 1];
                if (a > bb) { sidx[i] = bb; sidx[i + 1] = a; }
            }
            __syncthreads();
        }
        for (int i = tid; i < n; i += 256) g_src_sorted[start + i] = ds[sidx[i]];
    } else {
        for (int i = tid; i < n; i += 256) g_src_sorted[start + i] = ds[g_sorted[start + i]];
    }
}

// one block per segment, 512 threads = 4 batches x 128 dims, pure gather
__global__ void __launch_bounds__(512) segprod_kernel() {
    __shared__ int ssrc[512];
    int s   = blockIdx.x;
    int tid = threadIdx.x;
    int b   = tid >> 7;
    int d   = tid & 127;
    int start = g_seg_start[s], end = g_seg_start[s + 1];
    int n = end - start;
    float p[16];
    #pragma unroll
    for (int j = 0; j < 16; j++) p[j] = 1.f;
    const float* vb = g_vact + (size_t)b * ND * DIM + d;

    for (int base = 0; base < n; base += 512) {
        int cnt = min(512, n - base);
        __syncthreads();
        if (tid < cnt) ssrc[tid] = g_src_sorted[start + base + tid];
        __syncthreads();
        int i = 0;
        for (; i + 16 <= cnt; i += 16) {
            #pragma unroll
            for (int j = 0; j < 16; j++)
                p[j] *= vb[(size_t)ssrc[i + j] * DIM];
        }
        for (; i + 4 <= cnt; i += 4) {
            p[0] *= vb[(size_t)ssrc[i]     * DIM];
            p[1] *= vb[(size_t)ssrc[i + 1] * DIM];
            p[2] *= vb[(size_t)ssrc[i + 2] * DIM];
            p[3] *= vb[(size_t)ssrc[i + 3] * DIM];
        }
        for (; i < cnt; i++) p[0] *= vb[(size_t)ssrc[i] * DIM];
    }
    float r = ((p[0]*p[1]) * (p[2]*p[3])) * ((p[4]*p[5]) * (p[6]*p[7]));
    r *= ((p[8]*p[9]) * (p[10]*p[11])) * ((p[12]*p[13]) * (p[14]*p[15]));
    g_l[((size_t)b * NL + s) * DIM + d] = r;
}

// ---------------------------------------------------------------------------
extern "C" void kernel_launch(void* const* d_in, const int* in_sizes, int n_in,
                              void* d_out, int out_size)
{
    const float* v        = (const float*)d_in[0];
    const int*   data_src = (const int*)  d_in[1];
    const int*   data_dst = (const int*)  d_in[2];
    int base = (n_in >= 14 && in_sizes[3] == 1) ? 4 : 3;
    const float* rms1_w = (const float*)d_in[base + 0];
    const float* w1a    = (const float*)d_in[base + 1];
    const float* w2a    = (const float*)d_in[base + 2];
    const float* w3a    = (const float*)d_in[base + 3];
    const float* rms2_w = (const float*)d_in[base + 4];
    const float* w1b    = (const float*)d_in[base + 5];
    const float* w2b    = (const float*)d_in[base + 6];
    const float* w3b    = (const float*)d_in[base + 7];
    const float* wout   = (const float*)d_in[base + 8];
    const float* bout   = (const float*)d_in[base + 9];
    float* out = (float*)d_out;

    cudaFuncSetAttribute(ffn_mma_kernel<0>, cudaFuncAttributeMaxDynamicSharedMemorySize, SMEM_TC);
    cudaFuncSetAttribute(ffn_mma_kernel<1>, cudaFuncAttributeMaxDynamicSharedMemorySize, SMEM_TC);

    // Fork the bucketing chain onto a side stream; issue order keeps ffn1 as
    // launch #4 (ncu capture slot): init_hist(1), hist(2) [side]; prep(3),
    // ffn1(4) [main]; scan(5), scatter(6), seg_sort(7) [side]; join; segprod; ffn2.
    cudaStream_t s2 = nullptr;
    cudaEvent_t evFork = nullptr, evJoin = nullptr;
    bool par = (cudaStreamCreateWithFlags(&s2, cudaStreamNonBlocking) == cudaSuccess);
    if (par) par = (cudaEventCreateWithFlags(&evFork, cudaEventDisableTiming) == cudaSuccess);
    if (par) par = (cudaEventCreateWithFlags(&evJoin, cudaEventDisableTiming) == cudaSuccess);

    cudaStream_t bs = par ? s2 : (cudaStream_t)0;

    if (par) {
        cudaEventRecord(evFork, 0);
        cudaStreamWaitEvent(s2, evFork, 0);
    }

    init_hist_kernel<<<(NL + 255) / 256, 256, 0, bs>>>();
    hist_kernel<<<(EE + 1023) / 1024, 1024, 0, bs>>>(data_dst);

    prep_kernel<<<(6 * 49152 + 255) / 256, 256>>>(w1a, w2a, w3a, w1b, w2b, w3b);
    ffn_mma_kernel<0><<<NTOK / 128, 512, SMEM_TC>>>(v, rms1_w, nullptr, nullptr, nullptr);

    scan_kernel<<<1, 1024, 0, bs>>>();
    scatter_kernel<<<(EE + 1023) / 1024, 1024, 0, bs>>>(data_dst);
    seg_sort_kernel<<<NL, 256, 0, bs>>>(data_src);

    if (par) {
        cudaEventRecord(evJoin, s2);
        cudaStreamWaitEvent((cudaStream_t)0, evJoin, 0);
    }

    segprod_kernel<<<NL, 512>>>();
    ffn_mma_kernel<1><<<(BB * NL) / 128, 512, SMEM_TC>>>(nullptr, rms2_w, wout, bout, out);
}